// round 1
// baseline (speedup 1.0000x reference)
#include <cuda_runtime.h>
#include <math.h>

#define SEQ 2048
#define DIM 4096
#define NH  32
#define NKV 8
#define HD  128
#define KVD (NKV*HD)   // 1024

// Scratch (device globals; no allocation allowed)
__device__ float g_q[SEQ*DIM];
__device__ float g_k[SEQ*KVD];
__device__ float g_v[SEQ*KVD];
__device__ float g_attn[SEQ*DIM];

// ---------------------------------------------------------------------------
// SGEMM: C[M,N] = A[M,K] * B[K,N], all row-major. BM=BN=128, BK=16,
// 256 threads, each thread computes an 8x8 (2x2 quadrants of 4x4) tile.
// ---------------------------------------------------------------------------
__global__ __launch_bounds__(256) void sgemm_kernel(
    const float* __restrict__ A, const float* __restrict__ B,
    float* __restrict__ C, int M, int N, int K)
{
    const int BM = 128, BN = 128, BK = 16;
    __shared__ float As[BK][BM];   // transposed A tile
    __shared__ float Bs[BK][BN];

    int tid = threadIdx.x;
    int tx = tid & 15;         // 0..15 -> N
    int ty = tid >> 4;         // 0..15 -> M
    int row0 = blockIdx.y * BM;
    int col0 = blockIdx.x * BN;

    float acc[8][8];
#pragma unroll
    for (int i = 0; i < 8; i++)
#pragma unroll
        for (int j = 0; j < 8; j++) acc[i][j] = 0.0f;

    for (int k0 = 0; k0 < K; k0 += BK) {
        // Load A tile (128 x 16) transposed into As
#pragma unroll
        for (int it = 0; it < 2; ++it) {
            int slot = tid + it * 256;        // 0..511
            int r  = slot >> 2;               // 0..127
            int c4 = slot & 3;                // 0..3
            float4 v = *(const float4*)(A + (size_t)(row0 + r) * K + k0 + c4 * 4);
            As[c4*4+0][r] = v.x; As[c4*4+1][r] = v.y;
            As[c4*4+2][r] = v.z; As[c4*4+3][r] = v.w;
        }
        // Load B tile (16 x 128)
#pragma unroll
        for (int it = 0; it < 2; ++it) {
            int slot = tid + it * 256;        // 0..511
            int r  = slot >> 5;               // 0..15
            int c4 = slot & 31;               // 0..31
            *(float4*)(&Bs[r][c4*4]) =
                *(const float4*)(B + (size_t)(k0 + r) * N + col0 + c4 * 4);
        }
        __syncthreads();

#pragma unroll
        for (int kk = 0; kk < BK; kk++) {
            float a[8], b[8];
            *(float4*)&a[0] = *(float4*)&As[kk][ty*4];
            *(float4*)&a[4] = *(float4*)&As[kk][64 + ty*4];
            *(float4*)&b[0] = *(float4*)&Bs[kk][tx*4];
            *(float4*)&b[4] = *(float4*)&Bs[kk][64 + tx*4];
#pragma unroll
            for (int i = 0; i < 8; i++)
#pragma unroll
                for (int j = 0; j < 8; j++)
                    acc[i][j] += a[i] * b[j];
        }
        __syncthreads();
    }

    // Epilogue: 2x2 quadrants of 4x4, float4 stores
#pragma unroll
    for (int ih = 0; ih < 2; ih++) {
#pragma unroll
        for (int i = 0; i < 4; i++) {
            int r = row0 + ih*64 + ty*4 + i;
#pragma unroll
            for (int jh = 0; jh < 2; jh++) {
                float4 v = make_float4(acc[ih*4+i][jh*4+0], acc[ih*4+i][jh*4+1],
                                       acc[ih*4+i][jh*4+2], acc[ih*4+i][jh*4+3]);
                *(float4*)(C + (size_t)r * N + col0 + jh*64 + tx*4) = v;
            }
        }
    }
}

// ---------------------------------------------------------------------------
// RoPE (interleaved): for each (s, head, d<64):
//   even' = even*cos - odd*sin ; odd' = even*sin + odd*cos
// ---------------------------------------------------------------------------
__global__ void rope_kernel(float* __restrict__ t, const float* __restrict__ cs,
                            const float* __restrict__ sn, int nheads)
{
    int idx = blockIdx.x * blockDim.x + threadIdx.x;
    int total = SEQ * nheads * 64;
    if (idx >= total) return;
    int d = idx & 63;
    int h = (idx >> 6) % nheads;
    int s = idx / (64 * nheads);
    float c  = cs[s*64 + d];
    float si = sn[s*64 + d];
    float* p = t + ((size_t)s * nheads + h) * HD + 2*d;
    float e = p[0], o = p[1];
    p[0] = e*c - o*si;
    p[1] = e*si + o*c;
}

// ---------------------------------------------------------------------------
// Flash-style causal attention with the amplify override.
// Block: one head x one 64-query tile. 128 threads (tx=0..7 over cols/dims,
// ty=0..15 over rows). Online softmax in fp32.
// smem: QsT[128][64] | KV (KsT[128][64] then Vs[64][128]) | Ps[64][65]
// ---------------------------------------------------------------------------
#define FLASH_SMEM ((128*64 + 128*64 + 64*65) * 4)

__global__ __launch_bounds__(128) void flash_kernel(
    const float* __restrict__ gq, const float* __restrict__ gk,
    const float* __restrict__ gv, float* __restrict__ gout)
{
    extern __shared__ float sm[];
    float* QsT = sm;               // QsT[d*64 + r]
    float* KV  = sm + 128*64;      // K phase: KsT[d*64 + j]; V phase: Vs[j*128 + d]
    float* Ps  = sm + 2*128*64;    // Ps[r*65 + c]

    int qt  = blockIdx.x;
    int h   = blockIdx.y;
    int kvh = h >> 2;              // GQA: n_rep = 4
    int tid = threadIdx.x;
    int tx  = tid & 7;             // 0..7
    int ty  = tid >> 3;            // 0..15

    // Load Q tile transposed
#pragma unroll
    for (int it = 0; it < 16; ++it) {
        int slot = tid + it * 128;     // 0..2047
        int r  = slot >> 5;            // 0..63
        int c4 = slot & 31;            // 0..31
        float4 v = *(const float4*)(gq + (size_t)(qt*64 + r) * DIM + h*HD + c4*4);
        QsT[(c4*4+0)*64 + r] = v.x; QsT[(c4*4+1)*64 + r] = v.y;
        QsT[(c4*4+2)*64 + r] = v.z; QsT[(c4*4+3)*64 + r] = v.w;
    }

    float m[4], l[4], o[4][16];
#pragma unroll
    for (int i = 0; i < 4; i++) {
        m[i] = -1e30f; l[i] = 0.0f;
#pragma unroll
        for (int d = 0; d < 16; d++) o[i][d] = 0.0f;
    }
    const float scale = 0.08838834764831845f;  // 1/sqrt(128)

    for (int kt = 0; kt <= qt; ++kt) {
        __syncthreads();   // previous V reads (and Q load on iter 0) complete

        // Load K tile transposed into KV
#pragma unroll
        for (int it = 0; it < 16; ++it) {
            int slot = tid + it * 128;
            int r  = slot >> 5;
            int c4 = slot & 31;
            float4 v = *(const float4*)(gk + (size_t)(kt*64 + r) * KVD + kvh*HD + c4*4);
            KV[(c4*4+0)*64 + r] = v.x; KV[(c4*4+1)*64 + r] = v.y;
            KV[(c4*4+2)*64 + r] = v.z; KV[(c4*4+3)*64 + r] = v.w;
        }
        __syncthreads();

        // Scores: s[i][j] for rows r=ty+16i, local cols {tx*4+j, 32+tx*4+j}
        float s[4][8];
#pragma unroll
        for (int i = 0; i < 4; i++)
#pragma unroll
            for (int j = 0; j < 8; j++) s[i][j] = 0.0f;

#pragma unroll 4
        for (int kk = 0; kk < 128; ++kk) {
            float qv[4];
#pragma unroll
            for (int i = 0; i < 4; i++) qv[i] = QsT[kk*64 + ty + 16*i];
            float kvv[8];
            *(float4*)&kvv[0] = *(float4*)&KV[kk*64 + tx*4];
            *(float4*)&kvv[4] = *(float4*)&KV[kk*64 + 32 + tx*4];
#pragma unroll
            for (int i = 0; i < 4; i++)
#pragma unroll
                for (int j = 0; j < 8; j++)
                    s[i][j] += qv[i] * kvv[j];
        }

        // Scale + amplify override + causal mask; per-row tile max
        float mt[4];
#pragma unroll
        for (int i = 0; i < 4; i++) {
            int r = qt*64 + ty + 16*i;
            float mx = -1e30f;
#pragma unroll
            for (int j = 0; j < 8; j++) {
                int cl = (j < 4) ? (tx*4 + j) : (32 + tx*4 + (j - 4));
                int c  = kt*64 + cl;
                float v = s[i][j] * scale;
                if (c >= 2 && c < 100)
                    v = (sinf(3.14159265358979f * (float)(c - 2) * (1.0f/97.0f)) + 1.0f) * 500.0f;
                if (c > r) v -= 1e9f;
                s[i][j] = v;
                mx = fmaxf(mx, v);
            }
            mt[i] = mx;
        }
        // Reduce max across tx (lanes' low 3 bits)
#pragma unroll
        for (int i = 0; i < 4; i++) {
            float mx = mt[i];
            mx = fmaxf(mx, __shfl_xor_sync(0xffffffffu, mx, 1));
            mx = fmaxf(mx, __shfl_xor_sync(0xffffffffu, mx, 2));
            mx = fmaxf(mx, __shfl_xor_sync(0xffffffffu, mx, 4));
            mt[i] = mx;
        }

        float alpha[4];
#pragma unroll
        for (int i = 0; i < 4; i++) {
            float mn = fmaxf(m[i], mt[i]);
            alpha[i] = __expf(m[i] - mn);
            m[i] = mn;
        }
#pragma unroll
        for (int i = 0; i < 4; i++) {
            float acc = 0.0f;
#pragma unroll
            for (int j = 0; j < 8; j++) {
                float p = __expf(s[i][j] - m[i]);
                s[i][j] = p;
                acc += p;
            }
            acc += __shfl_xor_sync(0xffffffffu, acc, 1);
            acc += __shfl_xor_sync(0xffffffffu, acc, 2);
            acc += __shfl_xor_sync(0xffffffffu, acc, 4);
            l[i] = l[i] * alpha[i] + acc;
        }
        // Rescale accumulators
#pragma unroll
        for (int i = 0; i < 4; i++)
#pragma unroll
            for (int d = 0; d < 16; d++) o[i][d] *= alpha[i];

        // Store P tile to smem
#pragma unroll
        for (int i = 0; i < 4; i++)
#pragma unroll
            for (int j = 0; j < 8; j++) {
                int cl = (j < 4) ? (tx*4 + j) : (32 + tx*4 + (j - 4));
                Ps[(ty + 16*i)*65 + cl] = s[i][j];
            }
        __syncthreads();   // P visible; all K reads done -> safe to overwrite KV

        // Load V tile into KV as Vs[j][d]
#pragma unroll
        for (int it = 0; it < 16; ++it) {
            int slot = tid + it * 128;
            int r  = slot >> 5;
            int c4 = slot & 31;
            *(float4*)&KV[r*128 + c4*4] =
                *(const float4*)(gv + (size_t)(kt*64 + r) * KVD + kvh*HD + c4*4);
        }
        __syncthreads();

        // PV accumulate: o[i][ q*4+j2 ] over d = q*32 + tx*4 + j2
#pragma unroll 2
        for (int jj = 0; jj < 64; ++jj) {
            float pv[4];
#pragma unroll
            for (int i = 0; i < 4; i++) pv[i] = Ps[(ty + 16*i)*65 + jj];
            float vv[16];
#pragma unroll
            for (int q = 0; q < 4; q++)
                *(float4*)&vv[q*4] = *(float4*)&KV[jj*128 + q*32 + tx*4];
#pragma unroll
            for (int i = 0; i < 4; i++)
#pragma unroll
                for (int d = 0; d < 16; d++)
                    o[i][d] += pv[i] * vv[d];
        }
    }

    // Epilogue: divide by l, write out
#pragma unroll
    for (int i = 0; i < 4; i++) {
        float inv = 1.0f / l[i];
        int r = qt*64 + ty + 16*i;
#pragma unroll
        for (int q = 0; q < 4; q++) {
            float4 v = make_float4(o[i][q*4+0]*inv, o[i][q*4+1]*inv,
                                   o[i][q*4+2]*inv, o[i][q*4+3]*inv);
            *(float4*)(gout + (size_t)r * DIM + h*HD + q*32 + tx*4) = v;
        }
    }
}

// ---------------------------------------------------------------------------
extern "C" void kernel_launch(void* const* d_in, const int* in_sizes, int n_in,
                              void* d_out, int out_size)
{
    const float* x  = (const float*)d_in[0];
    const float* fc = (const float*)d_in[1];
    const float* fs = (const float*)d_in[2];
    // d_in[3] = mask (causal, reproduced analytically)
    const float* wq = (const float*)d_in[4];
    const float* wk = (const float*)d_in[5];
    const float* wv = (const float*)d_in[6];
    const float* wo = (const float*)d_in[7];
    float* out = (float*)d_out;

    float *gq, *gk, *gv, *ga;
    cudaGetSymbolAddress((void**)&gq, g_q);
    cudaGetSymbolAddress((void**)&gk, g_k);
    cudaGetSymbolAddress((void**)&gv, g_v);
    cudaGetSymbolAddress((void**)&ga, g_attn);

    // QKV projections
    sgemm_kernel<<<dim3(DIM/128, SEQ/128), 256>>>(x, wq, gq, SEQ, DIM, DIM);
    sgemm_kernel<<<dim3(KVD/128, SEQ/128), 256>>>(x, wk, gk, SEQ, KVD, DIM);
    sgemm_kernel<<<dim3(KVD/128, SEQ/128), 256>>>(x, wv, gv, SEQ, KVD, DIM);

    // RoPE on q and k
    rope_kernel<<<(SEQ*NH*64)/256, 256>>>(gq, fc, fs, NH);
    rope_kernel<<<(SEQ*NKV*64)/256, 256>>>(gk, fc, fs, NKV);

    // Attention
    cudaFuncSetAttribute(flash_kernel, cudaFuncAttributeMaxDynamicSharedMemorySize,
                         FLASH_SMEM);
    flash_kernel<<<dim3(SEQ/64, NH), 128, FLASH_SMEM>>>(gq, gk, gv, ga);

    // Output projection
    sgemm_kernel<<<dim3(DIM/128, SEQ/128), 256>>>(ga, wo, out, SEQ, DIM, DIM);
}

// round 2
// speedup vs baseline: 2.0205x; 2.0205x over previous
#include <cuda_runtime.h>
#include <math.h>
#include <stdint.h>

#define SEQ 2048
#define DIM 4096
#define NH  32
#define NKV 8
#define HD  128
#define KVD (NKV*HD)   // 1024

// Scratch (device globals; no allocation allowed)
__device__ float g_q[SEQ*DIM];
__device__ float g_k[SEQ*KVD];
__device__ float g_v[SEQ*KVD];
__device__ float g_attn[SEQ*DIM];

// ---------------------------------------------------------------------------
// TF32 tensor-core GEMM: C[M,N] = A[M,K]*B[K,N], row-major.
// 128x128x32 block tile, 256 threads = 8 warps (2 M x 4 N), warp tile 64x32,
// mma.sync.m16n8k8.tf32. cp.async 2-stage smem pipeline.
// Smem: A tile [128][36] (stride 36 == 4 mod 32 -> conflict-free A frags),
//       B tile [32][136] (stride 136 == 8 mod 32 -> conflict-free B frags).
// ---------------------------------------------------------------------------
#define GEMM_ASTRIDE 36
#define GEMM_BSTRIDE 136
#define GEMM_AFLOATS (128*GEMM_ASTRIDE)            // 4608
#define GEMM_STAGE   (GEMM_AFLOATS + 32*GEMM_BSTRIDE) // 8960 floats
#define GEMM_SMEM    (2*GEMM_STAGE*4)              // 71680 bytes

__device__ __forceinline__ uint32_t f2tf32(float f) {
    uint32_t r;
    asm("cvt.rna.tf32.f32 %0, %1;" : "=r"(r) : "f"(f));
    return r;
}

__device__ __forceinline__ void cp_async16(uint32_t dst, const void* src) {
    asm volatile("cp.async.cg.shared.global [%0], [%1], 16;" :: "r"(dst), "l"(src));
}

__global__ __launch_bounds__(256, 2) void mma_gemm(
    const float* __restrict__ A, const float* __restrict__ B,
    float* __restrict__ C, int M, int N, int K)
{
    extern __shared__ float sm[];
    uint32_t smem_u32 = (uint32_t)__cvta_generic_to_shared(sm);

    const int tid  = threadIdx.x;
    const int lane = tid & 31;
    const int warp = tid >> 5;
    const int gid  = lane >> 2;     // 0..7
    const int tig  = lane & 3;      // 0..3
    const int wm   = warp & 1;      // 2 warps along M
    const int wn   = warp >> 1;     // 4 warps along N
    const int row0 = blockIdx.y * 128;
    const int col0 = blockIdx.x * 128;

    // Global->smem load coordinates
    const int ar  = tid >> 3;       // 0..31 (A rows, +32/iter)
    const int ac4 = tid & 7;        // 0..7  (A col groups of 4)
    const int br  = tid >> 5;       // 0..7  (B rows, +8/iter)
    const int bc4 = tid & 31;       // 0..31 (B col groups of 4)

    float acc[4][4][4];
#pragma unroll
    for (int mi = 0; mi < 4; mi++)
#pragma unroll
        for (int ni = 0; ni < 4; ni++)
#pragma unroll
            for (int q = 0; q < 4; q++) acc[mi][ni][q] = 0.0f;

    const int T = K >> 5;

    auto prefetch = [&](int k0, int st) {
        uint32_t abase = smem_u32 + (uint32_t)(st * GEMM_STAGE) * 4u;
        uint32_t bbase = abase + GEMM_AFLOATS * 4u;
#pragma unroll
        for (int i = 0; i < 4; i++) {
            int r = ar + i * 32;
            cp_async16(abase + (uint32_t)(r * GEMM_ASTRIDE + ac4 * 4) * 4u,
                       A + (size_t)(row0 + r) * K + k0 + ac4 * 4);
        }
#pragma unroll
        for (int i = 0; i < 4; i++) {
            int r = br + i * 8;
            cp_async16(bbase + (uint32_t)(r * GEMM_BSTRIDE + bc4 * 4) * 4u,
                       B + (size_t)(k0 + r) * N + col0 + bc4 * 4);
        }
        asm volatile("cp.async.commit_group;");
    };

    prefetch(0, 0);

    for (int t = 0; t < T; t++) {
        if (t + 1 < T) {
            prefetch((t + 1) << 5, (t + 1) & 1);
            asm volatile("cp.async.wait_group 1;");
        } else {
            asm volatile("cp.async.wait_group 0;");
        }
        __syncthreads();

        const float* As = sm + (t & 1) * GEMM_STAGE;
        const float* Bs = As + GEMM_AFLOATS;

#pragma unroll
        for (int ks = 0; ks < 4; ks++) {
            const int kb = ks * 8;
            uint32_t af[4][4];
#pragma unroll
            for (int mi = 0; mi < 4; mi++) {
                int r = wm * 64 + mi * 16 + gid;
                const float* ap = As + r * GEMM_ASTRIDE + kb + tig;
                af[mi][0] = f2tf32(ap[0]);
                af[mi][1] = f2tf32(ap[8 * GEMM_ASTRIDE]);
                af[mi][2] = f2tf32(ap[4]);
                af[mi][3] = f2tf32(ap[8 * GEMM_ASTRIDE + 4]);
            }
            uint32_t bf[4][2];
#pragma unroll
            for (int ni = 0; ni < 4; ni++) {
                int c = wn * 32 + ni * 8 + gid;
                const float* bp = Bs + (kb + tig) * GEMM_BSTRIDE + c;
                bf[ni][0] = f2tf32(bp[0]);
                bf[ni][1] = f2tf32(bp[4 * GEMM_BSTRIDE]);
            }
#pragma unroll
            for (int mi = 0; mi < 4; mi++)
#pragma unroll
                for (int ni = 0; ni < 4; ni++) {
                    float* c = acc[mi][ni];
                    asm volatile(
                        "mma.sync.aligned.m16n8k8.row.col.f32.tf32.tf32.f32 "
                        "{%0,%1,%2,%3}, {%4,%5,%6,%7}, {%8,%9}, {%0,%1,%2,%3};\n"
                        : "+f"(c[0]), "+f"(c[1]), "+f"(c[2]), "+f"(c[3])
                        : "r"(af[mi][0]), "r"(af[mi][1]), "r"(af[mi][2]), "r"(af[mi][3]),
                          "r"(bf[ni][0]), "r"(bf[ni][1]));
                }
        }
        __syncthreads();
    }

    // Epilogue
#pragma unroll
    for (int mi = 0; mi < 4; mi++) {
        int r = row0 + wm * 64 + mi * 16 + gid;
#pragma unroll
        for (int ni = 0; ni < 4; ni++) {
            int c = col0 + wn * 32 + ni * 8 + tig * 2;
            *(float2*)(C + (size_t)r * N + c) =
                make_float2(acc[mi][ni][0], acc[mi][ni][1]);
            *(float2*)(C + (size_t)(r + 8) * N + c) =
                make_float2(acc[mi][ni][2], acc[mi][ni][3]);
        }
    }
}

// ---------------------------------------------------------------------------
// RoPE (interleaved)
// ---------------------------------------------------------------------------
__global__ void rope_kernel(float* __restrict__ t, const float* __restrict__ cs,
                            const float* __restrict__ sn, int nheads)
{
    int idx = blockIdx.x * blockDim.x + threadIdx.x;
    int total = SEQ * nheads * 64;
    if (idx >= total) return;
    int d = idx & 63;
    int h = (idx >> 6) % nheads;
    int s = idx / (64 * nheads);
    float c  = cs[s*64 + d];
    float si = sn[s*64 + d];
    float* p = t + ((size_t)s * nheads + h) * HD + 2*d;
    float e = p[0], o = p[1];
    p[0] = e*c - o*si;
    p[1] = e*si + o*c;
}

// ---------------------------------------------------------------------------
// Flash-style causal attention with the amplify override (fp32).
// ---------------------------------------------------------------------------
#define FLASH_SMEM ((128*64 + 128*64 + 64*65) * 4)

__global__ __launch_bounds__(128) void flash_kernel(
    const float* __restrict__ gq, const float* __restrict__ gk,
    const float* __restrict__ gv, float* __restrict__ gout)
{
    extern __shared__ float sm[];
    float* QsT = sm;               // QsT[d*64 + r]
    float* KV  = sm + 128*64;      // K phase: KsT[d*64 + j]; V phase: Vs[j*128 + d]
    float* Ps  = sm + 2*128*64;    // Ps[r*65 + c]

    int qt  = blockIdx.x;
    int h   = blockIdx.y;
    int kvh = h >> 2;              // GQA: n_rep = 4
    int tid = threadIdx.x;
    int tx  = tid & 7;             // 0..7
    int ty  = tid >> 3;            // 0..15

#pragma unroll
    for (int it = 0; it < 16; ++it) {
        int slot = tid + it * 128;
        int r  = slot >> 5;
        int c4 = slot & 31;
        float4 v = *(const float4*)(gq + (size_t)(qt*64 + r) * DIM + h*HD + c4*4);
        QsT[(c4*4+0)*64 + r] = v.x; QsT[(c4*4+1)*64 + r] = v.y;
        QsT[(c4*4+2)*64 + r] = v.z; QsT[(c4*4+3)*64 + r] = v.w;
    }

    float m[4], l[4], o[4][16];
#pragma unroll
    for (int i = 0; i < 4; i++) {
        m[i] = -1e30f; l[i] = 0.0f;
#pragma unroll
        for (int d = 0; d < 16; d++) o[i][d] = 0.0f;
    }
    const float scale = 0.08838834764831845f;

    for (int kt = 0; kt <= qt; ++kt) {
        __syncthreads();

#pragma unroll
        for (int it = 0; it < 16; ++it) {
            int slot = tid + it * 128;
            int r  = slot >> 5;
            int c4 = slot & 31;
            float4 v = *(const float4*)(gk + (size_t)(kt*64 + r) * KVD + kvh*HD + c4*4);
            KV[(c4*4+0)*64 + r] = v.x; KV[(c4*4+1)*64 + r] = v.y;
            KV[(c4*4+2)*64 + r] = v.z; KV[(c4*4+3)*64 + r] = v.w;
        }
        __syncthreads();

        float s[4][8];
#pragma unroll
        for (int i = 0; i < 4; i++)
#pragma unroll
            for (int j = 0; j < 8; j++) s[i][j] = 0.0f;

#pragma unroll 4
        for (int kk = 0; kk < 128; ++kk) {
            float qv[4];
#pragma unroll
            for (int i = 0; i < 4; i++) qv[i] = QsT[kk*64 + ty + 16*i];
            float kvv[8];
            *(float4*)&kvv[0] = *(float4*)&KV[kk*64 + tx*4];
            *(float4*)&kvv[4] = *(float4*)&KV[kk*64 + 32 + tx*4];
#pragma unroll
            for (int i = 0; i < 4; i++)
#pragma unroll
                for (int j = 0; j < 8; j++)
                    s[i][j] += qv[i] * kvv[j];
        }

        float mt[4];
#pragma unroll
        for (int i = 0; i < 4; i++) {
            int r = qt*64 + ty + 16*i;
            float mx = -1e30f;
#pragma unroll
            for (int j = 0; j < 8; j++) {
                int cl = (j < 4) ? (tx*4 + j) : (32 + tx*4 + (j - 4));
                int c  = kt*64 + cl;
                float v = s[i][j] * scale;
                if (c >= 2 && c < 100)
                    v = (sinf(3.14159265358979f * (float)(c - 2) * (1.0f/97.0f)) + 1.0f) * 500.0f;
                if (c > r) v -= 1e9f;
                s[i][j] = v;
                mx = fmaxf(mx, v);
            }
            mt[i] = mx;
        }
#pragma unroll
        for (int i = 0; i < 4; i++) {
            float mx = mt[i];
            mx = fmaxf(mx, __shfl_xor_sync(0xffffffffu, mx, 1));
            mx = fmaxf(mx, __shfl_xor_sync(0xffffffffu, mx, 2));
            mx = fmaxf(mx, __shfl_xor_sync(0xffffffffu, mx, 4));
            mt[i] = mx;
        }

        float alpha[4];
#pragma unroll
        for (int i = 0; i < 4; i++) {
            float mn = fmaxf(m[i], mt[i]);
            alpha[i] = __expf(m[i] - mn);
            m[i] = mn;
        }
#pragma unroll
        for (int i = 0; i < 4; i++) {
            float acc = 0.0f;
#pragma unroll
            for (int j = 0; j < 8; j++) {
                float p = __expf(s[i][j] - m[i]);
                s[i][j] = p;
                acc += p;
            }
            acc += __shfl_xor_sync(0xffffffffu, acc, 1);
            acc += __shfl_xor_sync(0xffffffffu, acc, 2);
            acc += __shfl_xor_sync(0xffffffffu, acc, 4);
            l[i] = l[i] * alpha[i] + acc;
        }
#pragma unroll
        for (int i = 0; i < 4; i++)
#pragma unroll
            for (int d = 0; d < 16; d++) o[i][d] *= alpha[i];

#pragma unroll
        for (int i = 0; i < 4; i++)
#pragma unroll
            for (int j = 0; j < 8; j++) {
                int cl = (j < 4) ? (tx*4 + j) : (32 + tx*4 + (j - 4));
                Ps[(ty + 16*i)*65 + cl] = s[i][j];
            }
        __syncthreads();

#pragma unroll
        for (int it = 0; it < 16; ++it) {
            int slot = tid + it * 128;
            int r  = slot >> 5;
            int c4 = slot & 31;
            *(float4*)&KV[r*128 + c4*4] =
                *(const float4*)(gv + (size_t)(kt*64 + r) * KVD + kvh*HD + c4*4);
        }
        __syncthreads();

#pragma unroll 2
        for (int jj = 0; jj < 64; ++jj) {
            float pv[4];
#pragma unroll
            for (int i = 0; i < 4; i++) pv[i] = Ps[(ty + 16*i)*65 + jj];
            float vv[16];
#pragma unroll
            for (int q = 0; q < 4; q++)
                *(float4*)&vv[q*4] = *(float4*)&KV[jj*128 + q*32 + tx*4];
#pragma unroll
            for (int i = 0; i < 4; i++)
#pragma unroll
                for (int d = 0; d < 16; d++)
                    o[i][d] += pv[i] * vv[d];
        }
    }

#pragma unroll
    for (int i = 0; i < 4; i++) {
        float inv = 1.0f / l[i];
        int r = qt*64 + ty + 16*i;
#pragma unroll
        for (int q = 0; q < 4; q++) {
            float4 v = make_float4(o[i][q*4+0]*inv, o[i][q*4+1]*inv,
                                   o[i][q*4+2]*inv, o[i][q*4+3]*inv);
            *(float4*)(gout + (size_t)r * DIM + h*HD + q*32 + tx*4) = v;
        }
    }
}

// ---------------------------------------------------------------------------
extern "C" void kernel_launch(void* const* d_in, const int* in_sizes, int n_in,
                              void* d_out, int out_size)
{
    const float* x  = (const float*)d_in[0];
    const float* fc = (const float*)d_in[1];
    const float* fs = (const float*)d_in[2];
    const float* wq = (const float*)d_in[4];
    const float* wk = (const float*)d_in[5];
    const float* wv = (const float*)d_in[6];
    const float* wo = (const float*)d_in[7];
    float* out = (float*)d_out;

    float *gq, *gk, *gv, *ga;
    cudaGetSymbolAddress((void**)&gq, g_q);
    cudaGetSymbolAddress((void**)&gk, g_k);
    cudaGetSymbolAddress((void**)&gv, g_v);
    cudaGetSymbolAddress((void**)&ga, g_attn);

    static bool attr_set = false;
    if (!attr_set) {
        cudaFuncSetAttribute(mma_gemm, cudaFuncAttributeMaxDynamicSharedMemorySize,
                             GEMM_SMEM);
        cudaFuncSetAttribute(flash_kernel, cudaFuncAttributeMaxDynamicSharedMemorySize,
                             FLASH_SMEM);
        attr_set = true;
    }

    // QKV projections (TF32 tensor cores)
    mma_gemm<<<dim3(DIM/128, SEQ/128), 256, GEMM_SMEM>>>(x, wq, gq, SEQ, DIM, DIM);
    mma_gemm<<<dim3(KVD/128, SEQ/128), 256, GEMM_SMEM>>>(x, wk, gk, SEQ, KVD, DIM);
    mma_gemm<<<dim3(KVD/128, SEQ/128), 256, GEMM_SMEM>>>(x, wv, gv, SEQ, KVD, DIM);

    // RoPE on q and k
    rope_kernel<<<(SEQ*NH*64)/256, 256>>>(gq, fc, fs, NH);
    rope_kernel<<<(SEQ*NKV*64)/256, 256>>>(gk, fc, fs, NKV);

    // Attention
    flash_kernel<<<dim3(SEQ/64, NH), 128, FLASH_SMEM>>>(gq, gk, gv, ga);

    // Output projection
    mma_gemm<<<dim3(DIM/128, SEQ/128), 256, GEMM_SMEM>>>(ga, wo, out, SEQ, DIM, DIM);
}

// round 3
// speedup vs baseline: 3.4486x; 1.7069x over previous
#include <cuda_runtime.h>
#include <math.h>
#include <stdint.h>

#define SEQ 2048
#define DIM 4096
#define NH  32
#define NKV 8
#define HD  128
#define KVD (NKV*HD)   // 1024

// Scratch (device globals; no allocation allowed)
__device__ float g_q[SEQ*DIM];
__device__ float g_k[SEQ*KVD];
__device__ float g_v[SEQ*KVD];
__device__ float g_attn[SEQ*DIM];

__device__ __forceinline__ uint32_t f2tf32(float f) {
    uint32_t r;
    asm("cvt.rna.tf32.f32 %0, %1;" : "=r"(r) : "f"(f));
    return r;
}

__device__ __forceinline__ void cp_async16(uint32_t dst, const void* src) {
    asm volatile("cp.async.cg.shared.global [%0], [%1], 16;" :: "r"(dst), "l"(src));
}

__device__ __forceinline__ void mma_tf32(float* c, const uint32_t* a, const uint32_t* b) {
    asm volatile(
        "mma.sync.aligned.m16n8k8.row.col.f32.tf32.tf32.f32 "
        "{%0,%1,%2,%3}, {%4,%5,%6,%7}, {%8,%9}, {%0,%1,%2,%3};\n"
        : "+f"(c[0]), "+f"(c[1]), "+f"(c[2]), "+f"(c[3])
        : "r"(a[0]), "r"(a[1]), "r"(a[2]), "r"(a[3]), "r"(b[0]), "r"(b[1]));
}

// ---------------------------------------------------------------------------
// TF32 tensor-core GEMM: C[M,N] = A[M,K]*B[K,N], row-major (unchanged, proven)
// ---------------------------------------------------------------------------
#define GEMM_ASTRIDE 36
#define GEMM_BSTRIDE 136
#define GEMM_AFLOATS (128*GEMM_ASTRIDE)
#define GEMM_STAGE   (GEMM_AFLOATS + 32*GEMM_BSTRIDE)
#define GEMM_SMEM    (2*GEMM_STAGE*4)

__global__ __launch_bounds__(256, 2) void mma_gemm(
    const float* __restrict__ A, const float* __restrict__ B,
    float* __restrict__ C, int M, int N, int K)
{
    extern __shared__ float sm[];
    uint32_t smem_u32 = (uint32_t)__cvta_generic_to_shared(sm);

    const int tid  = threadIdx.x;
    const int lane = tid & 31;
    const int warp = tid >> 5;
    const int gid  = lane >> 2;
    const int tig  = lane & 3;
    const int wm   = warp & 1;
    const int wn   = warp >> 1;
    const int row0 = blockIdx.y * 128;
    const int col0 = blockIdx.x * 128;

    const int ar  = tid >> 3;
    const int ac4 = tid & 7;
    const int br  = tid >> 5;
    const int bc4 = tid & 31;

    float acc[4][4][4];
#pragma unroll
    for (int mi = 0; mi < 4; mi++)
#pragma unroll
        for (int ni = 0; ni < 4; ni++)
#pragma unroll
            for (int q = 0; q < 4; q++) acc[mi][ni][q] = 0.0f;

    const int T = K >> 5;

    auto prefetch = [&](int k0, int st) {
        uint32_t abase = smem_u32 + (uint32_t)(st * GEMM_STAGE) * 4u;
        uint32_t bbase = abase + GEMM_AFLOATS * 4u;
#pragma unroll
        for (int i = 0; i < 4; i++) {
            int r = ar + i * 32;
            cp_async16(abase + (uint32_t)(r * GEMM_ASTRIDE + ac4 * 4) * 4u,
                       A + (size_t)(row0 + r) * K + k0 + ac4 * 4);
        }
#pragma unroll
        for (int i = 0; i < 4; i++) {
            int r = br + i * 8;
            cp_async16(bbase + (uint32_t)(r * GEMM_BSTRIDE + bc4 * 4) * 4u,
                       B + (size_t)(k0 + r) * N + col0 + bc4 * 4);
        }
        asm volatile("cp.async.commit_group;");
    };

    prefetch(0, 0);

    for (int t = 0; t < T; t++) {
        if (t + 1 < T) {
            prefetch((t + 1) << 5, (t + 1) & 1);
            asm volatile("cp.async.wait_group 1;");
        } else {
            asm volatile("cp.async.wait_group 0;");
        }
        __syncthreads();

        const float* As = sm + (t & 1) * GEMM_STAGE;
        const float* Bs = As + GEMM_AFLOATS;

#pragma unroll
        for (int ks = 0; ks < 4; ks++) {
            const int kb = ks * 8;
            uint32_t af[4][4];
#pragma unroll
            for (int mi = 0; mi < 4; mi++) {
                int r = wm * 64 + mi * 16 + gid;
                const float* ap = As + r * GEMM_ASTRIDE + kb + tig;
                af[mi][0] = f2tf32(ap[0]);
                af[mi][1] = f2tf32(ap[8 * GEMM_ASTRIDE]);
                af[mi][2] = f2tf32(ap[4]);
                af[mi][3] = f2tf32(ap[8 * GEMM_ASTRIDE + 4]);
            }
            uint32_t bf[4][2];
#pragma unroll
            for (int ni = 0; ni < 4; ni++) {
                int c = wn * 32 + ni * 8 + gid;
                const float* bp = Bs + (kb + tig) * GEMM_BSTRIDE + c;
                bf[ni][0] = f2tf32(bp[0]);
                bf[ni][1] = f2tf32(bp[4 * GEMM_BSTRIDE]);
            }
#pragma unroll
            for (int mi = 0; mi < 4; mi++)
#pragma unroll
                for (int ni = 0; ni < 4; ni++)
                    mma_tf32(acc[mi][ni], af[mi], bf[ni]);
        }
        __syncthreads();
    }

#pragma unroll
    for (int mi = 0; mi < 4; mi++) {
        int r = row0 + wm * 64 + mi * 16 + gid;
#pragma unroll
        for (int ni = 0; ni < 4; ni++) {
            int c = col0 + wn * 32 + ni * 8 + tig * 2;
            *(float2*)(C + (size_t)r * N + c) =
                make_float2(acc[mi][ni][0], acc[mi][ni][1]);
            *(float2*)(C + (size_t)(r + 8) * N + c) =
                make_float2(acc[mi][ni][2], acc[mi][ni][3]);
        }
    }
}

// ---------------------------------------------------------------------------
// RoPE (interleaved)
// ---------------------------------------------------------------------------
__global__ void rope_kernel(float* __restrict__ t, const float* __restrict__ cs,
                            const float* __restrict__ sn, int nheads)
{
    int idx = blockIdx.x * blockDim.x + threadIdx.x;
    int total = SEQ * nheads * 64;
    if (idx >= total) return;
    int d = idx & 63;
    int h = (idx >> 6) % nheads;
    int s = idx / (64 * nheads);
    float c  = cs[s*64 + d];
    float si = sn[s*64 + d];
    float* p = t + ((size_t)s * nheads + h) * HD + 2*d;
    float e = p[0], o = p[1];
    p[0] = e*c - o*si;
    p[1] = e*si + o*c;
}

// ---------------------------------------------------------------------------
// Tensor-core flash attention (TF32 mma for QK^T and P*V).
// Block: 128-query tile x one head. 256 threads = 8 warps; warp w owns rows
// [w*16, w*16+16). K/V processed in 64-key chunks. Online softmax in fp32.
// Smem (all values stored as tf32 bit patterns except P's fp32 stats path):
//   Qs[128][132], Ks[64][132], Vs[64][136], Ps[128][68]
// ---------------------------------------------------------------------------
#define FQ 128
#define FK 64
#define QSTR 132
#define KSTR 132
#define VSTR 136
#define PSTR 68
#define FLASH_SMEM ((FQ*QSTR + FK*KSTR + FK*VSTR + FQ*PSTR) * 4)

__global__ __launch_bounds__(256, 1) void flash_mma(
    const float* __restrict__ gq, const float* __restrict__ gk,
    const float* __restrict__ gv, float* __restrict__ gout)
{
    extern __shared__ float smf[];
    uint32_t* Qs = (uint32_t*)smf;
    uint32_t* Ks = Qs + FQ*QSTR;
    uint32_t* Vs = Ks + FK*KSTR;
    uint32_t* Ps = Vs + FK*VSTR;

    const int qt   = blockIdx.x;
    const int h    = blockIdx.y;
    const int kvh  = h >> 2;
    const int tid  = threadIdx.x;
    const int lane = tid & 31;
    const int warp = tid >> 5;
    const int gid  = lane >> 2;
    const int tig  = lane & 3;

    const int r0 = qt*128 + warp*16 + gid;   // global q row for c0/c1
    const int r1 = r0 + 8;                   // global q row for c2/c3

    // Load Q tile (128 x 128), convert to tf32, store row-major
#pragma unroll
    for (int it = 0; it < 16; ++it) {
        int slot = tid + it * 256;       // 0..4095
        int r  = slot >> 5;              // 0..127
        int c4 = slot & 31;              // 0..31
        float4 v = *(const float4*)(gq + (size_t)(qt*128 + r) * DIM + h*HD + c4*4);
        uint4 u = make_uint4(f2tf32(v.x), f2tf32(v.y), f2tf32(v.z), f2tf32(v.w));
        *(uint4*)(Qs + r*QSTR + c4*4) = u;
    }

    float m0 = -1e30f, m1 = -1e30f, l0 = 0.0f, l1 = 0.0f;
    float o[16][4];
#pragma unroll
    for (int nt = 0; nt < 16; nt++)
#pragma unroll
        for (int q = 0; q < 4; q++) o[nt][q] = 0.0f;

    const float scale = 0.08838834764831845f;  // 1/sqrt(128)
    const int nchunks = 2*qt + 2;

    for (int kt = 0; kt < nchunks; ++kt) {
        __syncthreads();   // previous PV reads of Vs complete (and Q ready)

        // Load K and V chunks (64 x 128 each), tf32-converted
#pragma unroll
        for (int it = 0; it < 8; ++it) {
            int slot = tid + it * 256;   // 0..2047
            int r  = slot >> 5;          // 0..63
            int c4 = slot & 31;
            float4 kv = *(const float4*)(gk + (size_t)(kt*64 + r) * KVD + kvh*HD + c4*4);
            *(uint4*)(Ks + r*KSTR + c4*4) =
                make_uint4(f2tf32(kv.x), f2tf32(kv.y), f2tf32(kv.z), f2tf32(kv.w));
            float4 vv = *(const float4*)(gv + (size_t)(kt*64 + r) * KVD + kvh*HD + c4*4);
            *(uint4*)(Vs + r*VSTR + c4*4) =
                make_uint4(f2tf32(vv.x), f2tf32(vv.y), f2tf32(vv.z), f2tf32(vv.w));
        }
        __syncthreads();

        // ---- S = Q * K^T  (128x64 per block; 16x64 per warp) ----
        float s[8][4];
#pragma unroll
        for (int nt = 0; nt < 8; nt++)
#pragma unroll
            for (int q = 0; q < 4; q++) s[nt][q] = 0.0f;

#pragma unroll
        for (int kb = 0; kb < 16; kb++) {
            const int k8 = kb * 8;
            uint32_t af[4];
            const uint32_t* qp = Qs + (warp*16 + gid)*QSTR + k8 + tig;
            af[0] = qp[0];
            af[1] = qp[8*QSTR];
            af[2] = qp[4];
            af[3] = qp[8*QSTR + 4];
#pragma unroll
            for (int nt = 0; nt < 8; nt++) {
                uint32_t bf[2];
                const uint32_t* kp = Ks + (nt*8 + gid)*KSTR + k8 + tig;
                bf[0] = kp[0];
                bf[1] = kp[4];
                mma_tf32(s[nt], af, bf);
            }
        }

        // ---- epilogue: scale + amplify + causal mask, online softmax ----
        float mx0 = -1e30f, mx1 = -1e30f;
#pragma unroll
        for (int nt = 0; nt < 8; nt++) {
            int cb = kt*64 + nt*8 + tig*2;
#pragma unroll
            for (int q = 0; q < 4; q++) {
                int c = cb + (q & 1);
                int r = (q < 2) ? r0 : r1;
                float v = s[nt][q] * scale;
                if (c >= 2 && c < 100)
                    v = (sinf((float)(c - 2) * (3.14159265358979f/97.0f)) + 1.0f) * 500.0f;
                if (c > r) v -= 1e9f;
                s[nt][q] = v;
                if (q < 2) mx0 = fmaxf(mx0, v); else mx1 = fmaxf(mx1, v);
            }
        }
        mx0 = fmaxf(mx0, __shfl_xor_sync(0xffffffffu, mx0, 1));
        mx0 = fmaxf(mx0, __shfl_xor_sync(0xffffffffu, mx0, 2));
        mx1 = fmaxf(mx1, __shfl_xor_sync(0xffffffffu, mx1, 1));
        mx1 = fmaxf(mx1, __shfl_xor_sync(0xffffffffu, mx1, 2));

        float mn0 = fmaxf(m0, mx0), mn1 = fmaxf(m1, mx1);
        float a0 = __expf(m0 - mn0), a1 = __expf(m1 - mn1);
        m0 = mn0; m1 = mn1;

        float sum0 = 0.0f, sum1 = 0.0f;
#pragma unroll
        for (int nt = 0; nt < 8; nt++) {
            float p0 = __expf(s[nt][0] - m0);
            float p1 = __expf(s[nt][1] - m0);
            float p2 = __expf(s[nt][2] - m1);
            float p3 = __expf(s[nt][3] - m1);
            sum0 += p0 + p1; sum1 += p2 + p3;
            s[nt][0] = p0; s[nt][1] = p1; s[nt][2] = p2; s[nt][3] = p3;
        }
        sum0 += __shfl_xor_sync(0xffffffffu, sum0, 1);
        sum0 += __shfl_xor_sync(0xffffffffu, sum0, 2);
        sum1 += __shfl_xor_sync(0xffffffffu, sum1, 1);
        sum1 += __shfl_xor_sync(0xffffffffu, sum1, 2);
        l0 = l0 * a0 + sum0;
        l1 = l1 * a1 + sum1;

        // rescale O accumulators
#pragma unroll
        for (int nt = 0; nt < 16; nt++) {
            o[nt][0] *= a0; o[nt][1] *= a0;
            o[nt][2] *= a1; o[nt][3] *= a1;
        }

        // store P (tf32) to smem — warp-private rows, warp-level sync suffices
#pragma unroll
        for (int nt = 0; nt < 8; nt++) {
            int cb = nt*8 + tig*2;
            uint2 u01 = make_uint2(f2tf32(s[nt][0]), f2tf32(s[nt][1]));
            uint2 u23 = make_uint2(f2tf32(s[nt][2]), f2tf32(s[nt][3]));
            *(uint2*)(Ps + (warp*16 + gid)*PSTR + cb)     = u01;
            *(uint2*)(Ps + (warp*16 + gid + 8)*PSTR + cb) = u23;
        }
        __syncwarp();

        // ---- O += P * V  (16x128 per warp; k = 64 keys) ----
#pragma unroll
        for (int kb = 0; kb < 8; kb++) {
            const int k8 = kb * 8;
            uint32_t pa[4];
            const uint32_t* pp = Ps + (warp*16 + gid)*PSTR + k8 + tig;
            pa[0] = pp[0];
            pa[1] = pp[8*PSTR];
            pa[2] = pp[4];
            pa[3] = pp[8*PSTR + 4];
#pragma unroll
            for (int nt = 0; nt < 16; nt++) {
                uint32_t vb[2];
                const uint32_t* vp = Vs + (k8 + tig)*VSTR + nt*8 + gid;
                vb[0] = vp[0];
                vb[1] = vp[4*VSTR];
                mma_tf32(o[nt], pa, vb);
            }
        }
    }

    // Final normalize + store
    float inv0 = 1.0f / l0, inv1 = 1.0f / l1;
#pragma unroll
    for (int nt = 0; nt < 16; nt++) {
        int c = h*HD + nt*8 + tig*2;
        *(float2*)(gout + (size_t)r0 * DIM + c) = make_float2(o[nt][0]*inv0, o[nt][1]*inv0);
        *(float2*)(gout + (size_t)r1 * DIM + c) = make_float2(o[nt][2]*inv1, o[nt][3]*inv1);
    }
}

// ---------------------------------------------------------------------------
extern "C" void kernel_launch(void* const* d_in, const int* in_sizes, int n_in,
                              void* d_out, int out_size)
{
    const float* x  = (const float*)d_in[0];
    const float* fc = (const float*)d_in[1];
    const float* fs = (const float*)d_in[2];
    const float* wq = (const float*)d_in[4];
    const float* wk = (const float*)d_in[5];
    const float* wv = (const float*)d_in[6];
    const float* wo = (const float*)d_in[7];
    float* out = (float*)d_out;

    float *gq, *gk, *gv, *ga;
    cudaGetSymbolAddress((void**)&gq, g_q);
    cudaGetSymbolAddress((void**)&gk, g_k);
    cudaGetSymbolAddress((void**)&gv, g_v);
    cudaGetSymbolAddress((void**)&ga, g_attn);

    cudaFuncSetAttribute(mma_gemm, cudaFuncAttributeMaxDynamicSharedMemorySize,
                         GEMM_SMEM);
    cudaFuncSetAttribute(flash_mma, cudaFuncAttributeMaxDynamicSharedMemorySize,
                         FLASH_SMEM);

    // QKV projections (TF32 tensor cores)
    mma_gemm<<<dim3(DIM/128, SEQ/128), 256, GEMM_SMEM>>>(x, wq, gq, SEQ, DIM, DIM);
    mma_gemm<<<dim3(KVD/128, SEQ/128), 256, GEMM_SMEM>>>(x, wk, gk, SEQ, KVD, DIM);
    mma_gemm<<<dim3(KVD/128, SEQ/128), 256, GEMM_SMEM>>>(x, wv, gv, SEQ, KVD, DIM);

    // RoPE on q and k
    rope_kernel<<<(SEQ*NH*64)/256, 256>>>(gq, fc, fs, NH);
    rope_kernel<<<(SEQ*NKV*64)/256, 256>>>(gk, fc, fs, NKV);

    // Attention (TF32 tensor cores)
    flash_mma<<<dim3(SEQ/128, NH), 256, FLASH_SMEM>>>(gq, gk, gv, ga);

    // Output projection
    mma_gemm<<<dim3(DIM/128, SEQ/128), 256, GEMM_SMEM>>>(ga, wo, out, SEQ, DIM, DIM);
}

// round 6
// speedup vs baseline: 6.2411x; 1.8097x over previous
#include <cuda_runtime.h>
#include <cuda_fp16.h>
#include <math.h>
#include <stdint.h>

#define SEQ 2048
#define DIM 4096
#define NH  32
#define NKV 8
#define HD  128
#define KVD (NKV*HD)   // 1024
#define GK  4096       // K for all projections

// fp16 scratch (device globals; no allocation allowed)
__device__ __half g_x16[SEQ*DIM];
__device__ __half g_wq16[DIM*DIM];
__device__ __half g_wk16[DIM*KVD];
__device__ __half g_wv16[DIM*KVD];
__device__ __half g_wo16[DIM*DIM];
__device__ __half g_q16[SEQ*DIM];
__device__ __half g_k16[SEQ*KVD];
__device__ __half g_v16[SEQ*KVD];
__device__ __half g_a16[SEQ*DIM];

__device__ __forceinline__ void cp_async16(uint32_t dst, const void* src) {
    asm volatile("cp.async.cg.shared.global [%0], [%1], 16;" :: "r"(dst), "l"(src));
}
__device__ __forceinline__ void ldsm4(uint32_t* r, uint32_t addr) {
    asm volatile("ldmatrix.sync.aligned.m8n8.x4.shared.b16 {%0,%1,%2,%3}, [%4];"
        : "=r"(r[0]), "=r"(r[1]), "=r"(r[2]), "=r"(r[3]) : "r"(addr));
}
__device__ __forceinline__ void ldsm4t(uint32_t* r, uint32_t addr) {
    asm volatile("ldmatrix.sync.aligned.m8n8.x4.trans.shared.b16 {%0,%1,%2,%3}, [%4];"
        : "=r"(r[0]), "=r"(r[1]), "=r"(r[2]), "=r"(r[3]) : "r"(addr));
}
__device__ __forceinline__ void mma16(float* c, const uint32_t* a, const uint32_t* b) {
    asm volatile(
        "mma.sync.aligned.m16n8k16.row.col.f32.f16.f16.f32 "
        "{%0,%1,%2,%3}, {%4,%5,%6,%7}, {%8,%9}, {%0,%1,%2,%3};\n"
        : "+f"(c[0]), "+f"(c[1]), "+f"(c[2]), "+f"(c[3])
        : "r"(a[0]), "r"(a[1]), "r"(a[2]), "r"(a[3]), "r"(b[0]), "r"(b[1]));
}

// ---------------------------------------------------------------------------
// fp32 -> fp16 convert (vectorized x8)
// ---------------------------------------------------------------------------
__global__ void cvt16(const float* __restrict__ in, __half* __restrict__ out, int n)
{
    int i = (blockIdx.x * blockDim.x + threadIdx.x) * 8;
    if (i >= n) return;
    float4 a = *(const float4*)(in + i);
    float4 b = *(const float4*)(in + i + 4);
    __half2 h[4];
    h[0] = __floats2half2_rn(a.x, a.y);
    h[1] = __floats2half2_rn(a.z, a.w);
    h[2] = __floats2half2_rn(b.x, b.y);
    h[3] = __floats2half2_rn(b.z, b.w);
    *(uint4*)(out + i) = *(uint4*)h;
}

// ---------------------------------------------------------------------------
// fp16 tensor-core GEMM: C[M,N] = A[M,4096] * B[4096,N], A/B fp16, accum fp32.
// Block 128x128, BK=32, 8 warps (2M x 4N), warp tile 64x32, m16n8k16.
// Smem: As[128][40] fp16 (pad 8), Bs[32][136] fp16 (pad 8); 2-stage cp.async.
// Fragments: A via ldmatrix, B via ldmatrix.trans (B stays [K][N]).
// ---------------------------------------------------------------------------
#define GA_STR 40
#define GB_STR 136
#define G_AH   (128*GA_STR)            // 5120 halfs
#define G_STAGEH (G_AH + 32*GB_STR)    // 9472 halfs
#define G_SMEM (2*G_STAGEH*2)          // 37888 bytes

__device__ __forceinline__ void cstore2(__half* C, size_t off, float a, float b) {
    *(__half2*)(C + off) = __floats2half2_rn(a, b);
}
__device__ __forceinline__ void cstore2(float* C, size_t off, float a, float b) {
    *(float2*)(C + off) = make_float2(a, b);
}

template<typename OutT>
__global__ __launch_bounds__(256, 2) void gemm16(
    const __half* __restrict__ A, const __half* __restrict__ B,
    OutT* __restrict__ C, int N)
{
    extern __shared__ __half sh[];
    uint32_t sbase = (uint32_t)__cvta_generic_to_shared(sh);

    const int tid  = threadIdx.x;
    const int lane = tid & 31;
    const int warp = tid >> 5;
    const int gid  = lane >> 2;
    const int tig  = lane & 3;
    const int wm   = warp & 1;
    const int wn   = warp >> 1;
    const int row0 = blockIdx.y * 128;
    const int col0 = blockIdx.x * 128;

    float acc[4][4][4];
#pragma unroll
    for (int mi = 0; mi < 4; mi++)
#pragma unroll
        for (int ni = 0; ni < 4; ni++)
#pragma unroll
            for (int q = 0; q < 4; q++) acc[mi][ni][q] = 0.0f;

    auto prefetch = [&](int t, int s) {
        int k0 = t * 32;
        uint32_t ab = sbase + (uint32_t)s * (G_STAGEH * 2);
        uint32_t bb = ab + G_AH * 2;
#pragma unroll
        for (int it = 0; it < 2; it++) {
            int slot = tid + it * 256;           // 0..511
            int r = slot >> 2, c = slot & 3;     // A: 128 rows x 4 chunks
            cp_async16(ab + (uint32_t)(r * 80 + c * 16),
                       A + (size_t)(row0 + r) * GK + k0 + c * 8);
        }
#pragma unroll
        for (int it = 0; it < 2; it++) {
            int slot = tid + it * 256;
            int r = slot >> 4, c = slot & 15;    // B: 32 rows x 16 chunks
            cp_async16(bb + (uint32_t)(r * 272 + c * 16),
                       B + (size_t)(k0 + r) * N + col0 + c * 8);
        }
        asm volatile("cp.async.commit_group;");
    };

    const int T = GK / 32;   // 128
    prefetch(0, 0);

    for (int t = 0; t < T; t++) {
        if (t + 1 < T) {
            prefetch(t + 1, (t + 1) & 1);
            asm volatile("cp.async.wait_group 1;");
        } else {
            asm volatile("cp.async.wait_group 0;");
        }
        __syncthreads();

        uint32_t ab = sbase + (uint32_t)(t & 1) * (G_STAGEH * 2);
        uint32_t bb = ab + G_AH * 2;

#pragma unroll
        for (int ks = 0; ks < 32; ks += 16) {
            uint32_t af[4][4];
#pragma unroll
            for (int mi = 0; mi < 4; mi++) {
                int r = wm * 64 + mi * 16 + (lane & 15);
                uint32_t addr = ab + (uint32_t)((r * GA_STR + ks + ((lane >> 4) << 3)) * 2);
                ldsm4(af[mi], addr);
            }
            uint32_t bf[4][2];
#pragma unroll
            for (int ntp = 0; ntp < 2; ntp++) {
                int kk = ks + (lane & 15);
                int cb = wn * 32 + ntp * 16 + ((lane >> 4) << 3);
                uint32_t addr = bb + (uint32_t)((kk * GB_STR + cb) * 2);
                uint32_t r4[4];
                ldsm4t(r4, addr);
                bf[ntp*2][0] = r4[0]; bf[ntp*2][1] = r4[1];
                bf[ntp*2+1][0] = r4[2]; bf[ntp*2+1][1] = r4[3];
            }
#pragma unroll
            for (int mi = 0; mi < 4; mi++)
#pragma unroll
                for (int ni = 0; ni < 4; ni++)
                    mma16(acc[mi][ni], af[mi], bf[ni]);
        }
        __syncthreads();
    }

#pragma unroll
    for (int mi = 0; mi < 4; mi++) {
        int r = row0 + wm * 64 + mi * 16 + gid;
#pragma unroll
        for (int ni = 0; ni < 4; ni++) {
            int c = col0 + wn * 32 + ni * 8 + tig * 2;
            cstore2(C, (size_t)r * N + c, acc[mi][ni][0], acc[mi][ni][1]);
            cstore2(C, (size_t)(r + 8) * N + c, acc[mi][ni][2], acc[mi][ni][3]);
        }
    }
}

// ---------------------------------------------------------------------------
// RoPE (interleaved) on fp16 buffers
// ---------------------------------------------------------------------------
__global__ void rope16(__half* __restrict__ t, const float* __restrict__ cs,
                       const float* __restrict__ sn, int nheads)
{
    int idx = blockIdx.x * blockDim.x + threadIdx.x;
    int total = SEQ * nheads * 64;
    if (idx >= total) return;
    int d = idx & 63;
    int h = (idx >> 6) % nheads;
    int s = idx / (64 * nheads);
    float c  = cs[s*64 + d];
    float si = sn[s*64 + d];
    __half2* p = (__half2*)(t + ((size_t)s * nheads + h) * HD + 2*d);
    float2 eo = __half22float2(*p);
    *p = __floats2half2_rn(eo.x*c - eo.y*si, eo.x*si + eo.y*c);
}

// ---------------------------------------------------------------------------
// fp16 tensor-core flash attention. Block: 128-q tile x head, 8 warps.
// QK^T: A=Q[row][dim] (plain 32b frag loads), B=K[key][dim] (plain loads).
// PV:   A=P[row][key] (plain), B=V[key][dim] via ldmatrix.trans.
// Smem halfs: Qs[128][136], Ks[64][136], Vs[64][136], Ps[128][72].
// ---------------------------------------------------------------------------
#define QSTR 136
#define KSTR 136
#define VSTR 136
#define PSTR 72
#define FLASH_SMEM ((128*QSTR + 64*KSTR + 64*VSTR + 128*PSTR) * 2)

__global__ __launch_bounds__(256, 1) void flash16(
    const __half* __restrict__ gq, const __half* __restrict__ gk,
    const __half* __restrict__ gv, __half* __restrict__ gout)
{
    extern __shared__ __half fsm[];
    __half* Qs = fsm;
    __half* Ks = Qs + 128*QSTR;
    __half* Vs = Ks + 64*KSTR;
    __half* Ps = Vs + 64*VSTR;
    uint32_t vbase = (uint32_t)__cvta_generic_to_shared(Vs);

    const int qt   = blockIdx.x;
    const int h    = blockIdx.y;
    const int kvh  = h >> 2;
    const int tid  = threadIdx.x;
    const int lane = tid & 31;
    const int warp = tid >> 5;
    const int gid  = lane >> 2;
    const int tig  = lane & 3;

    const int r0 = qt*128 + warp*16 + gid;
    const int r1 = r0 + 8;
    const int prow = warp*16 + gid;

    // Load Q tile (128 rows x 128 halfs = 16 chunks of 16B per row)
#pragma unroll
    for (int it = 0; it < 8; ++it) {
        int slot = tid + it * 256;       // 0..2047
        int r = slot >> 4, c = slot & 15;
        *(uint4*)(Qs + r*QSTR + c*8) =
            *(const uint4*)(gq + (size_t)(qt*128 + r) * DIM + h*HD + c*8);
    }

    float m0 = -1e30f, m1 = -1e30f, l0 = 0.0f, l1 = 0.0f;
    float o[16][4];
#pragma unroll
    for (int nt = 0; nt < 16; nt++)
#pragma unroll
        for (int q = 0; q < 4; q++) o[nt][q] = 0.0f;

    const float scale = 0.08838834764831845f;
    const int nchunks = 2*qt + 2;

    for (int kt = 0; kt < nchunks; ++kt) {
        __syncthreads();

#pragma unroll
        for (int it = 0; it < 4; ++it) {
            int slot = tid + it * 256;   // 0..1023
            int r = slot >> 4, c = slot & 15;
            *(uint4*)(Ks + r*KSTR + c*8) =
                *(const uint4*)(gk + (size_t)(kt*64 + r) * KVD + kvh*HD + c*8);
            *(uint4*)(Vs + r*VSTR + c*8) =
                *(const uint4*)(gv + (size_t)(kt*64 + r) * KVD + kvh*HD + c*8);
        }
        __syncthreads();

        // ---- S = Q * K^T (16x64 per warp), k = 128 dims in 8 k16 steps ----
        float s[8][4];
#pragma unroll
        for (int nt = 0; nt < 8; nt++)
#pragma unroll
            for (int q = 0; q < 4; q++) s[nt][q] = 0.0f;

#pragma unroll
        for (int kb = 0; kb < 8; kb++) {
            const int k = kb * 16;
            uint32_t af[4];
            const __half* qp = Qs + prow*QSTR + k + 2*tig;
            af[0] = *(const uint32_t*)(qp);
            af[1] = *(const uint32_t*)(qp + 8*QSTR);
            af[2] = *(const uint32_t*)(qp + 8);
            af[3] = *(const uint32_t*)(qp + 8*QSTR + 8);
#pragma unroll
            for (int nt = 0; nt < 8; nt++) {
                uint32_t bf[2];
                const __half* kp = Ks + (nt*8 + gid)*KSTR + k + 2*tig;
                bf[0] = *(const uint32_t*)(kp);
                bf[1] = *(const uint32_t*)(kp + 8);
                mma16(s[nt], af, bf);
            }
        }

        // ---- scale + amplify + causal mask, online softmax ----
        float mx0 = -1e30f, mx1 = -1e30f;
#pragma unroll
        for (int nt = 0; nt < 8; nt++) {
            int cb = kt*64 + nt*8 + tig*2;
#pragma unroll
            for (int q = 0; q < 4; q++) {
                int c = cb + (q & 1);
                int r = (q < 2) ? r0 : r1;
                float v = s[nt][q] * scale;
                if (c >= 2 && c < 100)
                    v = (sinf((float)(c - 2) * (3.14159265358979f/97.0f)) + 1.0f) * 500.0f;
                if (c > r) v -= 1e9f;
                s[nt][q] = v;
                if (q < 2) mx0 = fmaxf(mx0, v); else mx1 = fmaxf(mx1, v);
            }
        }
        mx0 = fmaxf(mx0, __shfl_xor_sync(0xffffffffu, mx0, 1));
        mx0 = fmaxf(mx0, __shfl_xor_sync(0xffffffffu, mx0, 2));
        mx1 = fmaxf(mx1, __shfl_xor_sync(0xffffffffu, mx1, 1));
        mx1 = fmaxf(mx1, __shfl_xor_sync(0xffffffffu, mx1, 2));

        float mn0 = fmaxf(m0, mx0), mn1 = fmaxf(m1, mx1);
        float a0 = __expf(m0 - mn0), a1 = __expf(m1 - mn1);
        m0 = mn0; m1 = mn1;

        float sum0 = 0.0f, sum1 = 0.0f;
#pragma unroll
        for (int nt = 0; nt < 8; nt++) {
            float p0 = __expf(s[nt][0] - m0);
            float p1 = __expf(s[nt][1] - m0);
            float p2 = __expf(s[nt][2] - m1);
            float p3 = __expf(s[nt][3] - m1);
            sum0 += p0 + p1; sum1 += p2 + p3;
            s[nt][0] = p0; s[nt][1] = p1; s[nt][2] = p2; s[nt][3] = p3;
        }
        sum0 += __shfl_xor_sync(0xffffffffu, sum0, 1);
        sum0 += __shfl_xor_sync(0xffffffffu, sum0, 2);
        sum1 += __shfl_xor_sync(0xffffffffu, sum1, 1);
        sum1 += __shfl_xor_sync(0xffffffffu, sum1, 2);
        l0 = l0 * a0 + sum0;
        l1 = l1 * a1 + sum1;

#pragma unroll
        for (int nt = 0; nt < 16; nt++) {
            o[nt][0] *= a0; o[nt][1] *= a0;
            o[nt][2] *= a1; o[nt][3] *= a1;
        }

        // store P as fp16 (warp-private rows)
#pragma unroll
        for (int nt = 0; nt < 8; nt++) {
            int cb = nt*8 + tig*2;
            *(__half2*)(Ps + prow*PSTR + cb)       = __floats2half2_rn(s[nt][0], s[nt][1]);
            *(__half2*)(Ps + (prow + 8)*PSTR + cb) = __floats2half2_rn(s[nt][2], s[nt][3]);
        }
        __syncwarp();

        // ---- O += P * V: k = 64 keys in 4 k16 steps; B frags via ldmatrix.trans
#pragma unroll
        for (int kb = 0; kb < 4; kb++) {
            const int k = kb * 16;
            uint32_t pa[4];
            const __half* pp = Ps + prow*PSTR + k + 2*tig;
            pa[0] = *(const uint32_t*)(pp);
            pa[1] = *(const uint32_t*)(pp + 8*PSTR);
            pa[2] = *(const uint32_t*)(pp + 8);
            pa[3] = *(const uint32_t*)(pp + 8*PSTR + 8);
#pragma unroll
            for (int ntp = 0; ntp < 8; ntp++) {
                int kk = k + (lane & 15);
                int cb = ntp*16 + ((lane >> 4) << 3);
                uint32_t vf[4];
                ldsm4t(vf, vbase + (uint32_t)((kk * VSTR + cb) * 2));
                mma16(o[ntp*2],   pa, vf + 0);
                mma16(o[ntp*2+1], pa, vf + 2);
            }
        }
    }

    // Final normalize + store fp16
    float inv0 = 1.0f / l0, inv1 = 1.0f / l1;
#pragma unroll
    for (int nt = 0; nt < 16; nt++) {
        int c = h*HD + nt*8 + tig*2;
        *(__half2*)(gout + (size_t)r0 * DIM + c) =
            __floats2half2_rn(o[nt][0]*inv0, o[nt][1]*inv0);
        *(__half2*)(gout + (size_t)r1 * DIM + c) =
            __floats2half2_rn(o[nt][2]*inv1, o[nt][3]*inv1);
    }
}

// ---------------------------------------------------------------------------
extern "C" void kernel_launch(void* const* d_in, const int* in_sizes, int n_in,
                              void* d_out, int out_size)
{
    const float* x  = (const float*)d_in[0];
    const float* fc = (const float*)d_in[1];
    const float* fs = (const float*)d_in[2];
    const float* wq = (const float*)d_in[4];
    const float* wk = (const float*)d_in[5];
    const float* wv = (const float*)d_in[6];
    const float* wo = (const float*)d_in[7];
    float* out = (float*)d_out;

    __half *x16, *wq16, *wk16, *wv16, *wo16, *q16, *k16, *v16, *a16;
    cudaGetSymbolAddress((void**)&x16,  g_x16);
    cudaGetSymbolAddress((void**)&wq16, g_wq16);
    cudaGetSymbolAddress((void**)&wk16, g_wk16);
    cudaGetSymbolAddress((void**)&wv16, g_wv16);
    cudaGetSymbolAddress((void**)&wo16, g_wo16);
    cudaGetSymbolAddress((void**)&q16,  g_q16);
    cudaGetSymbolAddress((void**)&k16,  g_k16);
    cudaGetSymbolAddress((void**)&v16,  g_v16);
    cudaGetSymbolAddress((void**)&a16,  g_a16);

    cudaFuncSetAttribute(flash16, cudaFuncAttributeMaxDynamicSharedMemorySize,
                         FLASH_SMEM);

    // fp32 -> fp16 converts
    cvt16<<<(SEQ*DIM/8 + 255)/256, 256>>>(x, x16, SEQ*DIM);
    cvt16<<<(DIM*DIM/8 + 255)/256, 256>>>(wq, wq16, DIM*DIM);
    cvt16<<<(DIM*KVD/8 + 255)/256, 256>>>(wk, wk16, DIM*KVD);
    cvt16<<<(DIM*KVD/8 + 255)/256, 256>>>(wv, wv16, DIM*KVD);
    cvt16<<<(DIM*DIM/8 + 255)/256, 256>>>(wo, wo16, DIM*DIM);

    // QKV projections (fp16 tensor cores, fp16 out)
    gemm16<__half><<<dim3(DIM/128, SEQ/128), 256, G_SMEM>>>(x16, wq16, q16, DIM);
    gemm16<__half><<<dim3(KVD/128, SEQ/128), 256, G_SMEM>>>(x16, wk16, k16, KVD);
    gemm16<__half><<<dim3(KVD/128, SEQ/128), 256, G_SMEM>>>(x16, wv16, v16, KVD);

    // RoPE on q and k (in-place fp16)
    rope16<<<(SEQ*NH*64)/256, 256>>>(q16, fc, fs, NH);
    rope16<<<(SEQ*NKV*64)/256, 256>>>(k16, fc, fs, NKV);

    // Attention (fp16 tensor cores) -> fp16 attn
    flash16<<<dim3(SEQ/128, NH), 256, FLASH_SMEM>>>(q16, k16, v16, a16);

    // Output projection (fp32 out)
    gemm16<float><<<dim3(DIM/128, SEQ/128), 256, G_SMEM>>>(a16, wo16, out, DIM);
}